// round 1
// baseline (speedup 1.0000x reference)
#include <cuda_runtime.h>
#include <cuda_bf16.h>
#include <cstdint>

#define BB 4
#define NN 2048
#define FF 128
#define HH 256
#define CC 64
#define MAXN 512

// ---------------- scratch (no allocations allowed) ----------------
__device__ float g_d[BB * NN];
__device__ float g_f1s[BB * NN];
__device__ float g_f1d[BB * NN];
__device__ float g_f2s[BB * NN];
__device__ float g_f2d[BB * NN];
__device__ int g_cnt[BB * NN];
__device__ unsigned short g_idx[(size_t)BB * NN * MAXN];
__device__ float g_T1[(size_t)BB * NN * FF];
__device__ float g_H1[(size_t)BB * NN * HH];
__device__ float g_T2[(size_t)BB * NN * HH];

// ---------------- block reductions ----------------
__device__ __forceinline__ float blockReduceSum(float v, volatile float* s) {
    int t = threadIdx.x, l = t & 31, w = t >> 5, nw = blockDim.x >> 5;
#pragma unroll
    for (int o = 16; o; o >>= 1) v += __shfl_xor_sync(0xffffffffu, v, o);
    __syncthreads();
    if (l == 0) s[w] = v;
    __syncthreads();
    if (t == 0) {
        float r = s[0];
        for (int q = 1; q < nw; q++) r += s[q];
        s[32] = r;
    }
    __syncthreads();
    return s[32];
}

__device__ __forceinline__ float blockReduceMax(float v, volatile float* s) {
    int t = threadIdx.x, l = t & 31, w = t >> 5, nw = blockDim.x >> 5;
#pragma unroll
    for (int o = 16; o; o >>= 1) v = fmaxf(v, __shfl_xor_sync(0xffffffffu, v, o));
    __syncthreads();
    if (l == 0) s[w] = v;
    __syncthreads();
    if (t == 0) {
        float r = s[0];
        for (int q = 1; q < nw; q++) r = fmaxf(r, s[q]);
        s[32] = r;
    }
    __syncthreads();
    return s[32];
}

// ---------------- k_zero: init graph_scores region ----------------
__global__ void k_zero(float* g) { g[threadIdx.x] = 0.0f; }

// ---------------- k_prep: degree, f1 dots, adjacency compaction ----------------
// grid: B*N blocks, 256 threads. Reads A exactly once.
__global__ __launch_bounds__(256) void k_prep(const float* __restrict__ A,
                                              const float* __restrict__ X,
                                              const float* __restrict__ a1s,
                                              const float* __restrict__ a1d) {
    int bi = blockIdx.x;
    int t = threadIdx.x;
    const float* Arow = A + (size_t)bi * NN;

    // each thread scans 8 consecutive columns (2 x float4)
    const float4* A4 = (const float4*)Arow + t * 2;
    float4 a0 = A4[0];
    float4 a1v = A4[1];
    float av[8] = {a0.x, a0.y, a0.z, a0.w, a1v.x, a1v.y, a1v.z, a1v.w};

    unsigned short loc[8];
    int lc = 0;
    float degs = 0.0f;
    int j0 = t * 8;
#pragma unroll
    for (int m = 0; m < 8; m++) {
        float a = av[m];
        degs += a;
        if (a > 0.0f) loc[lc++] = (unsigned short)(j0 + m);
    }

    // deterministic exclusive scan for compaction offsets
    __shared__ int s_s[256];
    s_s[t] = lc;
    __syncthreads();
    for (int off = 1; off < 256; off <<= 1) {
        int v = s_s[t];
        int v2 = (t >= off) ? s_s[t - off] : 0;
        __syncthreads();
        s_s[t] = v + v2;
        __syncthreads();
    }
    int total = s_s[255];
    int base = s_s[t] - lc;
    unsigned short* row = g_idx + (size_t)bi * MAXN;
    for (int m = 0; m < lc; m++)
        if (base + m < MAXN) row[base + m] = loc[m];

    __shared__ float s_red[33];
    float deg = blockReduceSum(degs, s_red);

    float ps = 0.0f, pd = 0.0f;
    if (t < FF) {
        float x = X[(size_t)bi * FF + t];
        ps = x * a1s[t];
        pd = x * a1d[t];
    }
    ps = blockReduceSum(ps, s_red);
    pd = blockReduceSum(pd, s_red);

    if (t == 0) {
        g_cnt[bi] = (total > MAXN) ? MAXN : total;
        g_d[bi] = rsqrtf(deg + 1.0f);
        g_f1s[bi] = ps;
        g_f1d[bi] = pd;
    }
}

// ---------------- k_gather: fused masked-softmax + sparse (att*Ahat) @ src ----------------
// L==1: src = X (arg), dims F; L==2: src = g_H1, dims H. One block per (b,i), DIM threads.
template <int DIM, int L>
__global__ __launch_bounds__(DIM) void k_gather(const float* __restrict__ xsrc) {
    int bi = blockIdx.x;
    int b = bi >> 11;
    int i = bi & (NN - 1);
    int t = threadIdx.x;

    const float* src = (L == 1) ? xsrc : (const float*)g_H1;
    const float* fs = (L == 1) ? g_f1s : g_f2s;
    const float* fd = (L == 1) ? g_f1d : g_f2d;
    float* dst = (L == 1) ? g_T1 : g_T2;

    const float* srcb = src + (size_t)b * NN * DIM;
    int cnt = g_cnt[bi];

    if (cnt == 0) {
        // all-masked row: softmax is uniform 1/N; Ahat row = only diagonal (deg=1, d=1)
        dst[(size_t)bi * DIM + t] = srcb[(size_t)i * DIM + t] * (1.0f / NN);
        return;
    }

    __shared__ float s_w[MAXN];
    __shared__ unsigned short s_j[MAXN];
    __shared__ float s_red[33];

    float fsrc = fs[bi];
    const unsigned short* idx = g_idx + (size_t)bi * MAXN;

    // phase 1: scores + max
    float lmax = -1e30f;
    for (int k = t; k < cnt; k += DIM) {
        int j = idx[k];
        s_j[k] = (unsigned short)j;
        float e = fsrc + fd[b * NN + j];
        e = e > 0.0f ? e : 0.2f * e;  // leaky relu 0.2
        s_w[k] = e;
        lmax = fmaxf(lmax, e);
    }
    float emax = blockReduceMax(lmax, s_red);

    // phase 2: exp + sum
    float lsum = 0.0f;
    for (int k = t; k < cnt; k += DIM) {
        float p = __expf(s_w[k] - emax);
        s_w[k] = p;
        lsum += p;
    }
    float denom = blockReduceSum(lsum, s_red);
    float inv = 1.0f / denom;
    float di = g_d[bi];

    // phase 3: final weights w = softmax * d_i * d_j * (1 + [i==j])
    for (int k = t; k < cnt; k += DIM) {
        int j = s_j[k];
        float w = s_w[k] * inv * di * g_d[b * NN + j];
        if (j == i) w *= 2.0f;
        s_w[k] = w;
    }
    __syncthreads();

    // phase 4: gather-accumulate (coalesced rows of src, L2-resident)
    float acc0 = 0.0f, acc1 = 0.0f, acc2 = 0.0f, acc3 = 0.0f;
    int k = 0;
    for (; k + 4 <= cnt; k += 4) {
        acc0 += s_w[k + 0] * srcb[(size_t)s_j[k + 0] * DIM + t];
        acc1 += s_w[k + 1] * srcb[(size_t)s_j[k + 1] * DIM + t];
        acc2 += s_w[k + 2] * srcb[(size_t)s_j[k + 2] * DIM + t];
        acc3 += s_w[k + 3] * srcb[(size_t)s_j[k + 3] * DIM + t];
    }
    for (; k < cnt; k++) acc0 += s_w[k] * srcb[(size_t)s_j[k] * DIM + t];
    dst[(size_t)bi * DIM + t] = (acc0 + acc1) + (acc2 + acc3);
}

// ---------------- k_dense1: H1 = relu(T1 @ W1 + b1); also f2 dots ----------------
// grid B*N blocks, 64 threads; each thread owns 4 output cols (float4).
__global__ __launch_bounds__(64) void k_dense1(const float* __restrict__ W1,
                                               const float* __restrict__ b1,
                                               const float* __restrict__ a2s,
                                               const float* __restrict__ a2d) {
    int bi = blockIdx.x;
    int t = threadIdx.x;
    __shared__ float s_t[FF];
    __shared__ float s_red[33];
    s_t[t] = g_T1[(size_t)bi * FF + t];
    s_t[t + 64] = g_T1[(size_t)bi * FF + t + 64];
    __syncthreads();

    float4 acc = ((const float4*)b1)[t];
    const float4* W4 = (const float4*)W1;
#pragma unroll 8
    for (int k = 0; k < FF; k++) {
        float x = s_t[k];
        float4 w = W4[k * (HH / 4) + t];
        acc.x += x * w.x;
        acc.y += x * w.y;
        acc.z += x * w.z;
        acc.w += x * w.w;
    }
    acc.x = fmaxf(acc.x, 0.0f);
    acc.y = fmaxf(acc.y, 0.0f);
    acc.z = fmaxf(acc.z, 0.0f);
    acc.w = fmaxf(acc.w, 0.0f);
    ((float4*)(g_H1 + (size_t)bi * HH))[t] = acc;

    float4 as = ((const float4*)a2s)[t];
    float4 ad = ((const float4*)a2d)[t];
    float ps = acc.x * as.x + acc.y * as.y + acc.z * as.z + acc.w * as.w;
    float pd = acc.x * ad.x + acc.y * ad.y + acc.z * ad.z + acc.w * ad.w;
    ps = blockReduceSum(ps, s_red);
    pd = blockReduceSum(pd, s_red);
    if (t == 0) {
        g_f2s[bi] = ps;
        g_f2d[bi] = pd;
    }
}

// ---------------- k_dense2: node = T2 @ W2 + b2 ----------------
// grid B*N/4 blocks (4 rows each), 64 threads = 4 rows x 16 col-groups (float4).
__global__ __launch_bounds__(64) void k_dense2(const float* __restrict__ W2,
                                               const float* __restrict__ b2,
                                               float* __restrict__ node) {
    int blk = blockIdx.x;
    int t = threadIdx.x;
    int r = t >> 4, c = t & 15;
    __shared__ float s[4 * HH];
    const float* T2b = g_T2 + (size_t)blk * 4 * HH;
    for (int idx = t; idx < 4 * HH; idx += 64) s[idx] = T2b[idx];
    __syncthreads();

    float4 acc = ((const float4*)b2)[c];
    const float4* W4 = (const float4*)W2;
    const float* srow = s + r * HH;
#pragma unroll 8
    for (int k = 0; k < HH; k++) {
        float x = srow[k];
        float4 w = W4[k * (CC / 4) + c];
        acc.x += x * w.x;
        acc.y += x * w.y;
        acc.z += x * w.z;
        acc.w += x * w.w;
    }
    ((float4*)(node + ((size_t)blk * 4 + r) * CC))[c] = acc;
}

// ---------------- k_graph: graph = sum_n node ----------------
// grid B*32 blocks, 64 threads; each block reduces a 64-row slab, atomicAdd into graph.
__global__ __launch_bounds__(64) void k_graph(const float* __restrict__ node,
                                              float* __restrict__ graph) {
    int b = blockIdx.x >> 5;
    int seg = blockIdx.x & 31;
    int c = threadIdx.x;
    const float* p = node + ((size_t)b * NN + (size_t)seg * 64) * CC + c;
    float acc = 0.0f;
#pragma unroll 8
    for (int n = 0; n < 64; n++) acc += p[(size_t)n * CC];
    atomicAdd(&graph[b * CC + c], acc);
}

// ---------------- launch ----------------
extern "C" void kernel_launch(void* const* d_in, const int* in_sizes, int n_in,
                              void* d_out, int out_size) {
    const float* X = (const float*)d_in[0];
    const float* A = (const float*)d_in[1];
    const float* a1s = (const float*)d_in[2];
    const float* a1d = (const float*)d_in[3];
    const float* W1 = (const float*)d_in[4];
    const float* b1 = (const float*)d_in[5];
    const float* a2s = (const float*)d_in[6];
    const float* a2d = (const float*)d_in[7];
    const float* W2 = (const float*)d_in[8];
    const float* b2 = (const float*)d_in[9];

    float* node = (float*)d_out;
    float* graph = node + (size_t)BB * NN * CC;

    k_zero<<<1, BB * CC>>>(graph);
    k_prep<<<BB * NN, 256>>>(A, X, a1s, a1d);
    k_gather<FF, 1><<<BB * NN, FF>>>(X);
    k_dense1<<<BB * NN, 64>>>(W1, b1, a2s, a2d);
    k_gather<HH, 2><<<BB * NN, HH>>>(nullptr);
    k_dense2<<<BB * NN / 4, 64>>>(W2, b2, node);
    k_graph<<<BB * 32, 64>>>(node, graph);
}

// round 2
// speedup vs baseline: 1.5363x; 1.5363x over previous
#include <cuda_runtime.h>
#include <cuda_bf16.h>
#include <cstdint>

#define BB 4
#define NN 2048
#define FF 128
#define HH 256
#define CC 64
#define MAXN 512
#define PAD 257

// ---------------- scratch (no allocations allowed) ----------------
__device__ float g_d[BB * NN];
__device__ float g_f1s[BB * NN];
__device__ float g_f1d[BB * NN];
__device__ float g_f2s[BB * NN];
__device__ float g_f2d[BB * NN];
__device__ int g_cnt[BB * NN];
__device__ unsigned short g_idx[(size_t)BB * NN * MAXN];
__device__ float g_T1[(size_t)BB * NN * FF];
__device__ float g_H1[(size_t)BB * NN * HH];
__device__ float g_P[(size_t)BB * NN * CC];

// ---------------- block reductions ----------------
__device__ __forceinline__ float blockReduceSum(float v, volatile float* s) {
    int t = threadIdx.x, l = t & 31, w = t >> 5, nw = blockDim.x >> 5;
#pragma unroll
    for (int o = 16; o; o >>= 1) v += __shfl_xor_sync(0xffffffffu, v, o);
    __syncthreads();
    if (l == 0) s[w] = v;
    __syncthreads();
    if (t == 0) {
        float r = s[0];
        for (int q = 1; q < nw; q++) r += s[q];
        s[32] = r;
    }
    __syncthreads();
    return s[32];
}

__device__ __forceinline__ float blockReduceMax(float v, volatile float* s) {
    int t = threadIdx.x, l = t & 31, w = t >> 5, nw = blockDim.x >> 5;
#pragma unroll
    for (int o = 16; o; o >>= 1) v = fmaxf(v, __shfl_xor_sync(0xffffffffu, v, o));
    __syncthreads();
    if (l == 0) s[w] = v;
    __syncthreads();
    if (t == 0) {
        float r = s[0];
        for (int q = 1; q < nw; q++) r = fmaxf(r, s[q]);
        s[32] = r;
    }
    __syncthreads();
    return s[32];
}

// ---------------- k_zero: init graph_scores region ----------------
__global__ void k_zero(float* g) { g[threadIdx.x] = 0.0f; }

// ---------------- k_prep: degree, f1 dots, adjacency compaction ----------------
__global__ __launch_bounds__(256) void k_prep(const float* __restrict__ A,
                                              const float* __restrict__ X,
                                              const float* __restrict__ a1s,
                                              const float* __restrict__ a1d) {
    int bi = blockIdx.x;
    int t = threadIdx.x;
    const float* Arow = A + (size_t)bi * NN;

    const float4* A4 = (const float4*)Arow + t * 2;
    float4 a0 = A4[0];
    float4 a1v = A4[1];
    float av[8] = {a0.x, a0.y, a0.z, a0.w, a1v.x, a1v.y, a1v.z, a1v.w};

    unsigned short loc[8];
    int lc = 0;
    float degs = 0.0f;
    int j0 = t * 8;
#pragma unroll
    for (int m = 0; m < 8; m++) {
        float a = av[m];
        degs += a;
        if (a > 0.0f) loc[lc++] = (unsigned short)(j0 + m);
    }

    __shared__ int s_s[256];
    s_s[t] = lc;
    __syncthreads();
    for (int off = 1; off < 256; off <<= 1) {
        int v = s_s[t];
        int v2 = (t >= off) ? s_s[t - off] : 0;
        __syncthreads();
        s_s[t] = v + v2;
        __syncthreads();
    }
    int total = s_s[255];
    int base = s_s[t] - lc;
    unsigned short* row = g_idx + (size_t)bi * MAXN;
    for (int m = 0; m < lc; m++)
        if (base + m < MAXN) row[base + m] = loc[m];

    __shared__ float s_red[33];
    float deg = blockReduceSum(degs, s_red);

    float ps = 0.0f, pd = 0.0f;
    if (t < FF) {
        float x = X[(size_t)bi * FF + t];
        ps = x * a1s[t];
        pd = x * a1d[t];
    }
    ps = blockReduceSum(ps, s_red);
    pd = blockReduceSum(pd, s_red);

    if (t == 0) {
        g_cnt[bi] = (total > MAXN) ? MAXN : total;
        g_d[bi] = rsqrtf(deg + 1.0f);
        g_f1s[bi] = ps;
        g_f1d[bi] = pd;
    }
}

// ---------------- k_gather: fused masked-softmax + sparse (att*Ahat) @ src ----------------
// DIM features (multiple of 4); KG parallel k-groups; block = (DIM/4)*KG threads.
// L==1: src = X (arg), dst = g_T1. L==2: src = g_P, dst = outp (node), +b2.
template <int DIM, int KG, int L>
__global__ __launch_bounds__((DIM / 4) * KG) void k_gather(const float* __restrict__ xsrc,
                                                           const float* __restrict__ b2,
                                                           float* __restrict__ outp) {
    constexpr int DIMV = DIM / 4;
    constexpr int T = DIMV * KG;
    int bi = blockIdx.x;
    int b = bi >> 11;
    int i = bi & (NN - 1);
    int t = threadIdx.x;

    const float* src = (L == 1) ? xsrc : (const float*)g_P;
    const float* fs = (L == 1) ? g_f1s : g_f2s;
    const float* fd = (L == 1) ? g_f1d : g_f2d;
    float* dst = (L == 1) ? (float*)g_T1 : outp;

    const float4* src4 = (const float4*)(src + (size_t)b * NN * DIM);
    int cnt = g_cnt[bi];

    if (cnt == 0) {
        // all-masked row: softmax uniform 1/N; Ahat row = only diagonal (deg=1)
        if (t < DIMV) {
            float4 xv = src4[(size_t)i * DIMV + t];
            float4 o = make_float4(xv.x * (1.0f / NN), xv.y * (1.0f / NN),
                                   xv.z * (1.0f / NN), xv.w * (1.0f / NN));
            if (L == 2) {
                float4 bb = ((const float4*)b2)[t];
                o.x += bb.x; o.y += bb.y; o.z += bb.z; o.w += bb.w;
            }
            ((float4*)(dst + (size_t)bi * DIM))[t] = o;
        }
        return;
    }

    __shared__ float s_w[MAXN];
    __shared__ unsigned short s_j[MAXN];
    __shared__ float s_red[33];
    __shared__ float4 s_acc[KG][DIMV];

    float fsrc = fs[bi];
    const unsigned short* idx = g_idx + (size_t)bi * MAXN;

    // phase 1: scores + max
    float lmax = -1e30f;
    for (int k = t; k < cnt; k += T) {
        int j = idx[k];
        s_j[k] = (unsigned short)j;
        float e = fsrc + fd[b * NN + j];
        e = e > 0.0f ? e : 0.2f * e;  // leaky relu 0.2
        s_w[k] = e;
        lmax = fmaxf(lmax, e);
    }
    float emax = blockReduceMax(lmax, s_red);

    // phase 2: exp + sum
    float lsum = 0.0f;
    for (int k = t; k < cnt; k += T) {
        float p = __expf(s_w[k] - emax);
        s_w[k] = p;
        lsum += p;
    }
    float denom = blockReduceSum(lsum, s_red);
    float inv = 1.0f / denom;
    float di = g_d[bi];

    // phase 3: final weights w = softmax * d_i * d_j * (1 + [i==j])
    for (int k = t; k < cnt; k += T) {
        int j = s_j[k];
        float w = s_w[k] * inv * di * g_d[b * NN + j];
        if (j == i) w *= 2.0f;
        s_w[k] = w;
    }
    __syncthreads();

    // phase 4: vectorized gather-accumulate across KG k-groups
    int v = t % DIMV;
    int g = t / DIMV;
    float4 a0 = make_float4(0.f, 0.f, 0.f, 0.f), a1 = a0, a2 = a0, a3 = a0;
    int k = g;
    for (; k + 3 * KG < cnt; k += 4 * KG) {
        float w0 = s_w[k], w1 = s_w[k + KG], w2 = s_w[k + 2 * KG], w3 = s_w[k + 3 * KG];
        float4 x0 = src4[(size_t)s_j[k] * DIMV + v];
        float4 x1 = src4[(size_t)s_j[k + KG] * DIMV + v];
        float4 x2 = src4[(size_t)s_j[k + 2 * KG] * DIMV + v];
        float4 x3 = src4[(size_t)s_j[k + 3 * KG] * DIMV + v];
        a0.x += w0 * x0.x; a0.y += w0 * x0.y; a0.z += w0 * x0.z; a0.w += w0 * x0.w;
        a1.x += w1 * x1.x; a1.y += w1 * x1.y; a1.z += w1 * x1.z; a1.w += w1 * x1.w;
        a2.x += w2 * x2.x; a2.y += w2 * x2.y; a2.z += w2 * x2.z; a2.w += w2 * x2.w;
        a3.x += w3 * x3.x; a3.y += w3 * x3.y; a3.z += w3 * x3.z; a3.w += w3 * x3.w;
    }
    for (; k < cnt; k += KG) {
        float w0 = s_w[k];
        float4 x0 = src4[(size_t)s_j[k] * DIMV + v];
        a0.x += w0 * x0.x; a0.y += w0 * x0.y; a0.z += w0 * x0.z; a0.w += w0 * x0.w;
    }
    a0.x += a1.x + a2.x + a3.x;
    a0.y += a1.y + a2.y + a3.y;
    a0.z += a1.z + a2.z + a3.z;
    a0.w += a1.w + a2.w + a3.w;
    s_acc[g][v] = a0;
    __syncthreads();

    if (t < DIMV) {
        float4 r = s_acc[0][t];
#pragma unroll
        for (int g2 = 1; g2 < KG; g2++) {
            float4 a = s_acc[g2][t];
            r.x += a.x; r.y += a.y; r.z += a.z; r.w += a.w;
        }
        if (L == 2) {
            float4 bb = ((const float4*)b2)[t];
            r.x += bb.x; r.y += bb.y; r.z += bb.z; r.w += bb.w;
        }
        ((float4*)(dst + (size_t)bi * DIM))[t] = r;
    }
}

// ---------------- k_dense1: H1 = relu(T1 @ W1 + b1) ----------------
// 1024 blocks x 128 threads; 8 rows/block; thread = (c 0..63 float4 col, rg 0..1 -> 4 rows)
__global__ __launch_bounds__(128) void k_dense1(const float* __restrict__ W1,
                                                const float* __restrict__ b1) {
    int blk = blockIdx.x;
    int t = threadIdx.x;
    int c = t & 63, rg = t >> 6;
    __shared__ float s_t[8 * FF];
    const float4* T14 = (const float4*)(g_T1 + (size_t)blk * 8 * FF);
    ((float4*)s_t)[t] = T14[t];
    ((float4*)s_t)[t + 128] = T14[t + 128];
    __syncthreads();

    float4 bb = ((const float4*)b1)[c];
    float4 acc0 = bb, acc1 = bb, acc2 = bb, acc3 = bb;
    const float4* W4 = (const float4*)W1;
    const float* xs = s_t + (rg * 4) * FF;
#pragma unroll 4
    for (int k = 0; k < FF; k++) {
        float4 w = W4[k * (HH / 4) + c];
        float x0 = xs[k], x1 = xs[FF + k], x2 = xs[2 * FF + k], x3 = xs[3 * FF + k];
        acc0.x += x0 * w.x; acc0.y += x0 * w.y; acc0.z += x0 * w.z; acc0.w += x0 * w.w;
        acc1.x += x1 * w.x; acc1.y += x1 * w.y; acc1.z += x1 * w.z; acc1.w += x1 * w.w;
        acc2.x += x2 * w.x; acc2.y += x2 * w.y; acc2.z += x2 * w.z; acc2.w += x2 * w.w;
        acc3.x += x3 * w.x; acc3.y += x3 * w.y; acc3.z += x3 * w.z; acc3.w += x3 * w.w;
    }
    float4* H4 = (float4*)(g_H1 + ((size_t)blk * 8 + rg * 4) * HH);
#define RELU4(a) a.x = fmaxf(a.x, 0.f); a.y = fmaxf(a.y, 0.f); a.z = fmaxf(a.z, 0.f); a.w = fmaxf(a.w, 0.f)
    RELU4(acc0); RELU4(acc1); RELU4(acc2); RELU4(acc3);
    H4[0 * (HH / 4) + c] = acc0;
    H4[1 * (HH / 4) + c] = acc1;
    H4[2 * (HH / 4) + c] = acc2;
    H4[3 * (HH / 4) + c] = acc3;
}

// ---------------- k_proj: P = H1 @ W2, plus f2 dots from smem-resident H1 rows ----------------
// 256 blocks x 128 threads; 32 rows/block; thread = (c 0..15 float4 col, rg 0..7 -> 4 rows)
__global__ __launch_bounds__(128) void k_proj(const float* __restrict__ W2,
                                              const float* __restrict__ a2s,
                                              const float* __restrict__ a2d) {
    int blk = blockIdx.x;
    int t = threadIdx.x;
    int c = t & 15, rg = t >> 4;
    __shared__ float s[32 * PAD];
    const float4* H4 = (const float4*)(g_H1 + (size_t)blk * 32 * HH);
    for (int idx = t; idx < 32 * (HH / 4); idx += 128) {
        float4 v = H4[idx];
        int r = idx / (HH / 4), kk = (idx % (HH / 4)) * 4;
        float* p = s + r * PAD + kk;
        p[0] = v.x; p[1] = v.y; p[2] = v.z; p[3] = v.w;
    }
    __syncthreads();

    float4 z = make_float4(0.f, 0.f, 0.f, 0.f);
    float4 acc0 = z, acc1 = z, acc2 = z, acc3 = z;
    const float4* W4 = (const float4*)W2;
    const float* xs = s + (rg * 4) * PAD;
#pragma unroll 4
    for (int k = 0; k < HH; k++) {
        float4 w = W4[k * (CC / 4) + c];
        float x0 = xs[k], x1 = xs[PAD + k], x2 = xs[2 * PAD + k], x3 = xs[3 * PAD + k];
        acc0.x += x0 * w.x; acc0.y += x0 * w.y; acc0.z += x0 * w.z; acc0.w += x0 * w.w;
        acc1.x += x1 * w.x; acc1.y += x1 * w.y; acc1.z += x1 * w.z; acc1.w += x1 * w.w;
        acc2.x += x2 * w.x; acc2.y += x2 * w.y; acc2.z += x2 * w.z; acc2.w += x2 * w.w;
        acc3.x += x3 * w.x; acc3.y += x3 * w.y; acc3.z += x3 * w.z; acc3.w += x3 * w.w;
    }
    float4* P4 = (float4*)(g_P + ((size_t)blk * 32 + rg * 4) * CC);
    P4[0 * (CC / 4) + c] = acc0;
    P4[1 * (CC / 4) + c] = acc1;
    P4[2 * (CC / 4) + c] = acc2;
    P4[3 * (CC / 4) + c] = acc3;

    // f2 dots: 4 threads per row, each covers 64 k's, quad shfl-reduce
    int r = t >> 2, q = t & 3;
    const float* row = s + r * PAD;
    float ps = 0.f, pd = 0.f;
    int k0 = q * 64;
#pragma unroll 8
    for (int k = k0; k < k0 + 64; k++) {
        float x = row[k];
        ps += x * a2s[k];
        pd += x * a2d[k];
    }
    ps += __shfl_xor_sync(0xffffffffu, ps, 1);
    ps += __shfl_xor_sync(0xffffffffu, ps, 2);
    pd += __shfl_xor_sync(0xffffffffu, pd, 1);
    pd += __shfl_xor_sync(0xffffffffu, pd, 2);
    if (q == 0) {
        int gi = blk * 32 + r;
        g_f2s[gi] = ps;
        g_f2d[gi] = pd;
    }
}

// ---------------- k_graph: graph = sum_n node ----------------
__global__ __launch_bounds__(64) void k_graph(const float* __restrict__ node,
                                              float* __restrict__ graph) {
    int b = blockIdx.x >> 5;
    int seg = blockIdx.x & 31;
    int c = threadIdx.x;
    const float* p = node + ((size_t)b * NN + (size_t)seg * 64) * CC + c;
    float acc = 0.0f;
#pragma unroll 8
    for (int n = 0; n < 64; n++) acc += p[(size_t)n * CC];
    atomicAdd(&graph[b * CC + c], acc);
}

// ---------------- launch ----------------
extern "C" void kernel_launch(void* const* d_in, const int* in_sizes, int n_in,
                              void* d_out, int out_size) {
    const float* X = (const float*)d_in[0];
    const float* A = (const float*)d_in[1];
    const float* a1s = (const float*)d_in[2];
    const float* a1d = (const float*)d_in[3];
    const float* W1 = (const float*)d_in[4];
    const float* b1 = (const float*)d_in[5];
    const float* a2s = (const float*)d_in[6];
    const float* a2d = (const float*)d_in[7];
    const float* W2 = (const float*)d_in[8];
    const float* b2 = (const float*)d_in[9];

    float* node = (float*)d_out;
    float* graph = node + (size_t)BB * NN * CC;

    k_zero<<<1, BB * CC>>>(graph);
    k_prep<<<BB * NN, 256>>>(A, X, a1s, a1d);
    k_gather<FF, 8, 1><<<BB * NN, (FF / 4) * 8>>>(X, nullptr, nullptr);
    k_dense1<<<BB * NN / 8, 128>>>(W1, b1);
    k_proj<<<BB * NN / 32, 128>>>(W2, a2s, a2d);
    k_gather<CC, 8, 2><<<BB * NN, (CC / 4) * 8>>>(nullptr, b2, node);
    k_graph<<<BB * 32, 64>>>(node, graph);
}